// round 17
// baseline (speedup 1.0000x reference)
#include <cuda_runtime.h>
#include <cuda_fp16.h>
#include <cstdint>

#define BB 8
#define TT 4096
#define DM 512
#define NROWS (BB * TT)

// fp16 scratch. Q pre-scaled by (1/sqrt(512))*log2(e). K/V COMPACTED over
// valid keys; V TRANSPOSED [b][d][j]. g_Wt: W transposed fp16 [which][n][k].
__device__ __align__(256) __half g_Qh[NROWS * 64];
__device__ __align__(256) __half g_Kc[NROWS * 64];
__device__ __align__(256) __half g_Vtc[BB * 64 * TT];
__device__ __align__(256) __half g_Wt[3 * 64 * DM];
__device__ int      g_tidx[NROWS];        // compact j -> original t (tail = 0)
__device__ int      g_total[BB];          // valid count
__device__ int      g_nt[BB];             // ceil(valid/64)
__device__ uint32_t g_biasc[NROWS / 2];   // compacted f16x2 bias (tail = -64k)
// split-K partials
__device__ __align__(256) float g_Op[2 * NROWS * 64];   // unnormalized O
__device__ float g_lp[2 * NROWS];                       // row sums

// ---------------------------------------------------------------------------
// helpers
// ---------------------------------------------------------------------------
__device__ __forceinline__ uint32_t smem_to_u32(const void* p) {
    uint32_t a;
    asm("{ .reg .u64 t; cvta.to.shared.u64 t, %1; cvt.u32.u64 %0, t; }" : "=r"(a) : "l"(p));
    return a;
}
__device__ __forceinline__ uint32_t pack_h2(float lo, float hi) {
    uint32_t d; asm("cvt.rn.f16x2.f32 %0, %1, %2;" : "=r"(d) : "f"(hi), "f"(lo)); return d;
}
__device__ __forceinline__ uint32_t hadd2(uint32_t a, uint32_t b) {
    uint32_t d; asm("add.rn.f16x2 %0, %1, %2;" : "=r"(d) : "r"(a), "r"(b)); return d;
}
__device__ __forceinline__ uint32_t h2exp2(uint32_t a) {
    uint32_t d; asm("ex2.approx.f16x2 %0, %1;" : "=r"(d) : "r"(a)); return d;
}
// fp16: D += A(m16 x k16) * B(k16 x n8), f32 accumulate
__device__ __forceinline__ void mma16(float* d, const uint32_t* a, const uint32_t* b) {
    asm volatile(
        "mma.sync.aligned.m16n8k16.row.col.f32.f16.f16.f32 "
        "{%0,%1,%2,%3}, {%4,%5,%6,%7}, {%8,%9}, {%0,%1,%2,%3};"
        : "+f"(d[0]), "+f"(d[1]), "+f"(d[2]), "+f"(d[3])
        : "r"(a[0]), "r"(a[1]), "r"(a[2]), "r"(a[3]), "r"(b[0]), "r"(b[1]));
}
__device__ __forceinline__ void cp16(uint32_t dst, const void* src) {
    asm volatile("cp.async.ca.shared.global [%0], [%1], 16;" :: "r"(dst), "l"(src));
}
__device__ __forceinline__ void cp_commit() { asm volatile("cp.async.commit_group;"); }
template<int N> __device__ __forceinline__ void cp_wait() {
    asm volatile("cp.async.wait_group %0;" :: "n"(N));
}

// ---------------------------------------------------------------------------
// Fused prep: blocks 0-23 transpose W to fp16 g_Wt; blocks 24-31 run the
// per-batch key-compaction scan (tidx, total, nt, bias; zero K/V pad region).
// ---------------------------------------------------------------------------
__global__ void __launch_bounds__(256) prep_kernel(
    const float* __restrict__ Wq, const float* __restrict__ Wk,
    const float* __restrict__ Wv, const int* __restrict__ pm_g)
{
    int tid = threadIdx.x;
    if (blockIdx.x < 24) {
        __shared__ float tile[64][65];
        int which = blockIdx.x >> 3;
        int kb    = (blockIdx.x & 7) * 64;
        const float* W = (which == 0) ? Wq : ((which == 1) ? Wk : Wv);
        __half* Wt = g_Wt + (size_t)which * 64 * DM;

        #pragma unroll
        for (int i = 0; i < 16; i++) {
            int idx = tid + i * 256;
            int k = idx >> 6, n = idx & 63;
            tile[k][n] = W[(size_t)(kb + k) * 64 + n];
        }
        __syncthreads();
        #pragma unroll
        for (int i = 0; i < 16; i++) {
            int idx = tid + i * 256;
            int n = idx >> 6, k = idx & 63;
            Wt[(size_t)n * DM + kb + k] = __float2half_rn(tile[k][n]);
        }
    } else {
        int b = blockIdx.x - 24;
        const int* m = pm_g + (size_t)b * TT;
        int base = tid * 16;

        int v[16];
        int cnt = 0;
        #pragma unroll
        for (int i = 0; i < 16; i += 4) {
            int4 mm = *(const int4*)(m + base + i);
            v[i] = (mm.x == 0); v[i + 1] = (mm.y == 0);
            v[i + 2] = (mm.z == 0); v[i + 3] = (mm.w == 0);
            cnt += v[i] + v[i + 1] + v[i + 2] + v[i + 3];
        }

        __shared__ int ssum[256];
        ssum[tid] = cnt;
        __syncthreads();
        for (int off = 1; off < 256; off <<= 1) {
            int t = (tid >= off) ? ssum[tid - off] : 0;
            __syncthreads();
            ssum[tid] += t;
            __syncthreads();
        }
        int total = ssum[255];
        int o = ssum[tid] - cnt;

        int* tidx = g_tidx + (size_t)b * TT;
        #pragma unroll
        for (int i = 0; i < 16; i++) {
            if (v[i]) tidx[o++] = base + i;
        }
        int tileEnd = ((total + 127) >> 7) << 7;
        for (int j = total + tid; j < tileEnd; j += 256) tidx[j] = 0;

        int nt = (total + 63) >> 6;
        if (tid == 0) { g_nt[b] = nt; g_total[b] = total; }
        int padEnd = nt * 64;

        uint32_t* bc = g_biasc + (size_t)b * (TT / 2);
        for (int j2 = tid; j2 < (padEnd >> 1); j2 += 256) {
            int j0 = 2 * j2;
            uint32_t w = 0;
            if (j0 >= total)     w |= 0x0000FBFFu;
            if (j0 + 1 >= total) w |= 0xFBFF0000u;
            bc[j2] = w;
        }

        for (int j = total + tid; j < padEnd; j += 256) {
            uint32_t* kr = (uint32_t*)(g_Kc + ((size_t)b * TT + j) * 64);
            #pragma unroll
            for (int c = 0; c < 32; c++) kr[c] = 0;
        }
        int P = padEnd - total;
        if (P > 0) {
            for (int x = tid; x < P * 64; x += 256) {
                int d = x / P, j = total + x % P;
                g_Vtc[((size_t)b * 64 + d) * TT + j] = __ushort_as_half((unsigned short)0);
            }
        }
    }
}

// ---------------------------------------------------------------------------
// Projection, fp16 m16n8k16, 2-stage cp.async pipeline.
// which==0: full Q. which==1/2: COMPACTED K/V (gather via g_tidx).
// ---------------------------------------------------------------------------
#define PX_PAD 36
#define PWT_STR 40
#define P_X0 0
#define P_X1 18432
#define P_W0 36864
#define P_W1 41984
#define P_TIDX 47104
#define P_TOT  47616

__global__ void __launch_bounds__(256, 2) proj_kernel(
    const float* __restrict__ Xq, const float* __restrict__ Xk, const float* __restrict__ Xv)
{
    extern __shared__ char sm[];
    uint32_t smb = smem_to_u32(sm);

    const int which = blockIdx.y;
    const int tid = threadIdx.x, lane = tid & 31, warp = tid >> 5;
    const int r4 = lane >> 2, k4 = lane & 3;

    const float* X;
    int rowBase;
    int b = 0, total = 0;
    int* tidx_s = (int*)(sm + P_TIDX);

    if (which == 0) {
        X = Xq;
        rowBase = blockIdx.x * 128;
    } else {
        b = blockIdx.x >> 5;
        int tile = blockIdx.x & 31;
        total = g_total[b];
        rowBase = tile * 128;
        if (rowBase >= total) return;
        X = ((which == 1) ? Xk : Xv) + (size_t)b * TT * DM;
        if (tid < 128) tidx_s[tid] = g_tidx[(size_t)b * TT + rowBase + tid];
        __syncthreads();
    }
    const __half* Wt = g_Wt + (size_t)which * 64 * DM;

    auto load_chunk = [&](int ch) {
        uint32_t xd = smb + ((ch & 1) ? P_X1 : P_X0);
        uint32_t wd = smb + ((ch & 1) ? P_W1 : P_W0);
        #pragma unroll
        for (int i = 0; i < 4; i++) {
            int idx = tid + i * 256;
            int row = idx >> 3, c = idx & 7;
            const float* src;
            if (which == 0)
                src = X + (size_t)(rowBase + row) * DM + ch * 32 + c * 4;
            else
                src = X + (size_t)tidx_s[row] * DM + ch * 32 + c * 4;
            cp16(xd + row * (PX_PAD * 4) + c * 16, src);
        }
        {
            int n = tid >> 2, seg = tid & 3;
            cp16(wd + n * (PWT_STR * 2) + seg * 16, Wt + (size_t)n * DM + ch * 32 + seg * 8);
        }
        cp_commit();
    };

    float acc[8][4];
    #pragma unroll
    for (int nb = 0; nb < 8; nb++)
        #pragma unroll
        for (int i = 0; i < 4; i++) acc[nb][i] = 0.0f;

    load_chunk(0);
    for (int ch = 0; ch < 16; ch++) {
        if (ch > 0) __syncthreads();
        if (ch < 15) load_chunk(ch + 1);
        if (ch < 15) cp_wait<1>(); else cp_wait<0>();
        __syncthreads();

        const float*  Xs = (const float*)(sm + ((ch & 1) ? P_X1 : P_X0));
        const __half* Ws = (const __half*)(sm + ((ch & 1) ? P_W1 : P_W0));

        #pragma unroll
        for (int ks = 0; ks < 2; ks++) {
            int c0 = ks * 16 + 2 * k4;
            const float* xp  = Xs + (warp * 16 + r4) * PX_PAD + c0;
            const float* xp8 = xp + 8 * PX_PAD;
            uint32_t a[4] = {
                pack_h2(xp[0],  xp[1]),
                pack_h2(xp8[0], xp8[1]),
                pack_h2(xp[8],  xp[9]),
                pack_h2(xp8[8], xp8[9])
            };
            #pragma unroll
            for (int nb = 0; nb < 8; nb++) {
                const __half* wn = Ws + (nb * 8 + r4) * PWT_STR + c0;
                uint32_t bb[2] = { *(const uint32_t*)(wn), *(const uint32_t*)(wn + 8) };
                mma16(acc[nb], a, bb);
            }
        }
    }

    if (which == 0) {
        int m0 = rowBase + warp * 16 + r4;
        const float sc = 0.044194173824159216f * 1.4426950408889634f;
        __half* yp = g_Qh + (size_t)m0 * 64;
        #pragma unroll
        for (int nb = 0; nb < 8; nb++) {
            int c = nb * 8 + 2 * k4;
            *(uint32_t*)(yp + c)          = pack_h2(acc[nb][0] * sc, acc[nb][1] * sc);
            *(uint32_t*)(yp + 8 * 64 + c) = pack_h2(acc[nb][2] * sc, acc[nb][3] * sc);
        }
    } else {
        int j0 = rowBase + warp * 16 + r4;
        int j1 = j0 + 8;
        bool w0 = j0 < total, w1 = j1 < total;
        if (which == 1) {
            __half* y0 = g_Kc + ((size_t)b * TT + j0) * 64;
            __half* y1 = g_Kc + ((size_t)b * TT + j1) * 64;
            #pragma unroll
            for (int nb = 0; nb < 8; nb++) {
                int c = nb * 8 + 2 * k4;
                if (w0) *(uint32_t*)(y0 + c) = pack_h2(acc[nb][0], acc[nb][1]);
                if (w1) *(uint32_t*)(y1 + c) = pack_h2(acc[nb][2], acc[nb][3]);
            }
        } else {
            __half* vb = g_Vtc + (size_t)b * 64 * TT;
            #pragma unroll
            for (int nb = 0; nb < 8; nb++) {
                int d = nb * 8 + 2 * k4;
                if (w0) {
                    vb[(size_t)d * TT + j0]       = __float2half_rn(acc[nb][0]);
                    vb[(size_t)(d + 1) * TT + j0] = __float2half_rn(acc[nb][1]);
                }
                if (w1) {
                    vb[(size_t)d * TT + j1]       = __float2half_rn(acc[nb][2]);
                    vb[(size_t)(d + 1) * TT + j1] = __float2half_rn(acc[nb][3]);
                }
            }
        }
    }
}

// ---------------------------------------------------------------------------
// Flash attention, SPLIT-K over compacted keys. Grid (32, 8, 2): z = KV half.
// CTA = 128 q-rows, 4 warps x m32 x n64, 128 threads, 3 CTAs/SM.
// Writes UNNORMALIZED O + row-sum l partials; combine_kernel finishes.
// Q fragments read from SMEM per tile (register relief for occupancy 3).
// ---------------------------------------------------------------------------
#define AQ_STR 72
#define AK_STR 72
#define AV_STR 72
#define A_BIAS 0                       // 2048 u32 = 8192 B
#define A_Q    8192
#define A_K0   26624
#define A_K1   35840
#define A_V0   45056
#define A_V1   54272
#define A_TOT  63488

__global__ void __launch_bounds__(128, 3) attn_kernel()
{
    extern __shared__ char sm[];
    uint32_t smb = smem_to_u32(sm);

    const int tid = threadIdx.x, lane = tid & 31, warp = tid >> 5;
    const int b = blockIdx.y, qBase = blockIdx.x * 128, z = blockIdx.z;
    const int r4 = lane >> 2, k4 = lane & 3;

    const int nt  = g_nt[b];
    const int nth = (nt + 1) >> 1;
    const int t0  = z ? nth : 0;
    const int t1  = z ? nt : nth;

    float* Op = g_Op + (size_t)z * NROWS * 64 + ((size_t)b * TT + qBase) * 64;
    float* lp = g_lp + (size_t)z * NROWS + (size_t)b * TT + qBase;

    if (t0 >= t1) {   // empty half: zero partials
        for (int i = tid; i < 128 * 64; i += 128) Op[i] = 0.0f;
        if (tid < 128) lp[tid] = 0.0f;
        return;
    }

    const __half* gK  = g_Kc  + (size_t)b * TT * 64;
    const __half* gVt = g_Vtc + (size_t)b * 64 * TT;

    // stage Q tile (fp16, pre-scaled)
    {
        const __half* src = g_Qh + ((size_t)b * TT + qBase) * 64;
        #pragma unroll
        for (int i = 0; i < 8; i++) {
            int idx = tid + i * 128;
            int row = idx >> 3, c = idx & 7;
            cp16(smb + A_Q + row * (AQ_STR * 2) + c * 16, src + row * 64 + c * 8);
        }
        cp_commit();
    }

    auto load_tile = [&](int t) {
        int base = t * 64;
        uint32_t kd = smb + ((t & 1) ? A_K1 : A_K0);
        uint32_t vd = smb + ((t & 1) ? A_V1 : A_V0);
        #pragma unroll
        for (int i = 0; i < 4; i++) {
            int idx = tid + i * 128;
            int row = idx >> 3, c = idx & 7;
            cp16(kd + row * (AK_STR * 2) + c * 16, gK + (size_t)(base + row) * 64 + c * 8);
        }
        #pragma unroll
        for (int i = 0; i < 4; i++) {
            int idx = tid + i * 128;
            int d = idx >> 3, c = idx & 7;
            cp16(vd + d * (AV_STR * 2) + c * 16, gVt + (size_t)d * TT + base + c * 8);
        }
        cp_commit();
    };

    load_tile(t0);

    // stage compacted bias (full nt range; cheap)
    {
        uint32_t* b16 = (uint32_t*)(sm + A_BIAS);
        const uint32_t* src = g_biasc + (size_t)b * (TT / 2);
        for (int i = tid; i < nt * 32; i += 128) b16[i] = src[i];
    }

    cp_wait<1>();
    __syncthreads();

    const __half* Qs = (const __half*)(sm + A_Q);

    float o[2][8][4];
    float la[4] = {0.f, 0.f, 0.f, 0.f};
    float lb[4] = {0.f, 0.f, 0.f, 0.f};
    #pragma unroll
    for (int m2 = 0; m2 < 2; m2++)
        #pragma unroll
        for (int nb = 0; nb < 8; nb++)
            #pragma unroll
            for (int i = 0; i < 4; i++) o[m2][nb][i] = 0.0f;

    const uint32_t ONES = 0x3C003C00u;
    const uint32_t onesb[2] = { ONES, ONES };

    for (int t = t0; t < t1; t++) {
        if (t > t0) __syncthreads();
        if (t < t1 - 1) load_tile(t + 1);
        if (t < t1 - 1) cp_wait<1>(); else cp_wait<0>();
        __syncthreads();

        const __half* Ks = (const __half*)(sm + ((t & 1) ? A_K1 : A_K0));
        const __half* Vs = (const __half*)(sm + ((t & 1) ? A_V1 : A_V0));
        const uint32_t* bias16 = (const uint32_t*)(sm + A_BIAS) + t * 32;

        // ---- S = Q @ K^T: Q frags from SMEM; K B-frags feed both m16s ----
        float s[2][8][4];
        #pragma unroll
        for (int m2 = 0; m2 < 2; m2++)
            #pragma unroll
            for (int nb = 0; nb < 8; nb++) {
                s[m2][nb][0] = 0.0f; s[m2][nb][1] = 0.0f;
                s[m2][nb][2] = 0.0f; s[m2][nb][3] = 0.0f;
            }
        #pragma unroll
        for (int ks = 0; ks < 4; ks++) {
            int c0 = ks * 16 + 2 * k4;
            uint32_t a[2][4];
            #pragma unroll
            for (int m2 = 0; m2 < 2; m2++) {
                const __half* qp = Qs + (warp * 32 + m2 * 16 + r4) * AQ_STR + c0;
                a[m2][0] = *(const uint32_t*)(qp);
                a[m2][1] = *(const uint32_t*)(qp + 8 * AQ_STR);
                a[m2][2] = *(const uint32_t*)(qp + 8);
                a[m2][3] = *(const uint32_t*)(qp + 8 * AQ_STR + 8);
            }
            #pragma unroll
            for (int nb = 0; nb < 8; nb++) {
                const __half* kk = Ks + (nb * 8 + r4) * AK_STR + c0;
                uint32_t bb[2] = { *(const uint32_t*)(kk), *(const uint32_t*)(kk + 8) };
                mma16(s[0][nb], a[0], bb);
                mma16(s[1][nb], a[1], bb);
            }
        }

        // ---- softmax in f16x2 ----
        uint32_t plo[2][8], phi[2][8];
        #pragma unroll
        for (int nb = 0; nb < 8; nb++) {
            uint32_t bv = bias16[nb * 4 + k4];
            #pragma unroll
            for (int m2 = 0; m2 < 2; m2++) {
                plo[m2][nb] = h2exp2(hadd2(pack_h2(s[m2][nb][0], s[m2][nb][1]), bv));
                phi[m2][nb] = h2exp2(hadd2(pack_h2(s[m2][nb][2], s[m2][nb][3]), bv));
            }
        }

        // ---- O += P @ V; l += P @ 1 ----
        #pragma unroll
        for (int nbS = 0; nbS < 4; nbS++) {
            uint32_t a0[4] = { plo[0][2 * nbS], phi[0][2 * nbS],
                               plo[0][2 * nbS + 1], phi[0][2 * nbS + 1] };
            uint32_t a1[4] = { plo[1][2 * nbS], phi[1][2 * nbS],
                               plo[1][2 * nbS + 1], phi[1][2 * nbS + 1] };
            int sc = nbS * 16 + 2 * k4;
            #pragma unroll
            for (int nb = 0; nb < 8; nb++) {
                const __half* vp = Vs + (nb * 8 + r4) * AV_STR + sc;
                uint32_t bb[2] = { *(const uint32_t*)(vp), *(const uint32_t*)(vp + 8) };
                mma16(o[0][nb], a0, bb);
                mma16(o[1][nb], a1, bb);
            }
            mma16(la, a0, onesb);
            mma16(lb, a1, onesb);
        }
    }

    // write UNNORMALIZED partials
    if (k4 == 0) {
        lp[warp * 32 + r4]      = la[0];
        lp[warp * 32 + r4 + 8]  = la[2];
        lp[warp * 32 + 16 + r4]     = lb[0];
        lp[warp * 32 + 16 + r4 + 8] = lb[2];
    }
    #pragma unroll
    for (int m2 = 0; m2 < 2; m2++) {
        float* op = Op + (size_t)(warp * 32 + m2 * 16) * 64;
        #pragma unroll
        for (int nb = 0; nb < 8; nb++) {
            int c = nb * 8 + 2 * k4;
            float* oo = m2 ? &o[1][nb][0] : &o[0][nb][0];
            *(float2*)(op + r4 * 64 + c)       = make_float2(oo[0], oo[1]);
            *(float2*)(op + (r4 + 8) * 64 + c) = make_float2(oo[2], oo[3]);
        }
    }
}

// ---------------------------------------------------------------------------
// Combine: out = (O0 + O1) / (l0 + l1). float4 per thread.
// ---------------------------------------------------------------------------
__global__ void __launch_bounds__(256) combine_kernel(float* __restrict__ out)
{
    int idx = blockIdx.x * 256 + threadIdx.x;       // float4 index
    int row = idx >> 4;
    float inv = 1.0f / (g_lp[row] + g_lp[NROWS + row]);
    const float4* o0 = (const float4*)g_Op;
    const float4* o1 = (const float4*)(g_Op + (size_t)NROWS * 64);
    float4 a = o0[idx], b = o1[idx];
    ((float4*)out)[idx] = make_float4((a.x + b.x) * inv, (a.y + b.y) * inv,
                                      (a.z + b.z) * inv, (a.w + b.w) * inv);
}

// ---------------------------------------------------------------------------
// kernel_launch: inputs (metadata order): k, v, q, pad_mask, Wk, Wq, Wv
// ---------------------------------------------------------------------------
extern "C" void kernel_launch(void* const* d_in, const int* in_sizes, int n_in,
                              void* d_out, int out_size)
{
    const float* k        = (const float*)d_in[0];
    const float* v        = (const float*)d_in[1];
    const float* q        = (const float*)d_in[2];
    const int*   pad_mask = (const int*)d_in[3];
    const float* Wk       = (const float*)d_in[4];
    const float* Wq       = (const float*)d_in[5];
    const float* Wv       = (const float*)d_in[6];
    float* out = (float*)d_out;

    prep_kernel<<<32, 256>>>(Wq, Wk, Wv, pad_mask);

    cudaFuncSetAttribute(proj_kernel, cudaFuncAttributeMaxDynamicSharedMemorySize, P_TOT);
    dim3 pg(BB * TT / 128, 3);
    proj_kernel<<<pg, 256, P_TOT>>>(q, k, v);

    cudaFuncSetAttribute(attn_kernel, cudaFuncAttributeMaxDynamicSharedMemorySize, A_TOT);
    dim3 ag(TT / 128, BB, 2);
    attn_kernel<<<ag, 128, A_TOT>>>();

    combine_kernel<<<NROWS * 16 / 256, 256>>>(out);
}